// round 8
// baseline (speedup 1.0000x reference)
#include <cuda_runtime.h>
#include <math.h>

#define BB 256
#define TT 64
#define HH 256
#define DD 8

struct GruP {
    const float *Wih0, *Whh0, *bih0, *bhh0;
    const float *Wih1, *Whh1, *bih1, *bhh1;
};

// Persistent state (device globals: allocation-free scratch)
__device__ float g_h   [2*2*BB*HH];          // [s][l][b][h]  carried (post-attention) hidden
__device__ float g_hnew[2*2*BB*HH];          // [s][l][b][h]  fresh GRU hidden this step
__device__ float g_ctx [2*2*BB*HH];          // [s][o][b][h]  attention context
__device__ float g_es  [2*2*BB*HH];          // [s][l][b][g]  query projection
__device__ float g_buf [2*BB*TT*2*HH];       // [s][b][t][l][h]  hidden history
__device__ float g_eh  [2*BB*TT*2*HH];       // [s][b][t][l][g]  cached history projection
__device__ float g_out [2*TT*BB*HH];         // [s][t][b][h]  top-layer GRU outputs

__device__ __forceinline__ float sigm(float x) { return 1.0f / (1.0f + __expf(-x)); }
__device__ __forceinline__ float tanh_fast(float x) {
    float y;
    asm("tanh.approx.f32 %0, %1;" : "=f"(y) : "f"(x));
    return y;
}

__global__ void k_init() {
    int i = blockIdx.x * blockDim.x + threadIdx.x;
    if (i < 2*2*BB*HH) g_h[i] = 0.0f;
}

// ---------------------------------------------------------------------------
// K1: GRU layer 0. gh = h_prev @ Whh0^T fused with gate math.
// Tile 32b x 32h x 3gates. W transposed in smem -> float2 loads.
// grid (8 h, 8 b, 2 s), 256 threads, thread = 2b x 2h x 3g micro-tile.
// ---------------------------------------------------------------------------
__global__ __launch_bounds__(256) void k1_layer0(const float* __restrict__ recv,
                                                 GruP p1, GruP p2, int step) {
    const int s = blockIdx.z;
    const GruP P = s ? p2 : p1;
    __shared__ float As[32][33];        // [b][k]
    __shared__ float Ws[3][32][34];     // [g][k][h]  (transposed, float2-aligned)
    const int tid = threadIdx.x;
    const int tx = tid & 15, ty = tid >> 4;
    const int b0 = blockIdx.y * 32, hc0 = blockIdx.x * 32;
    const float* __restrict__ hprev = g_h + s * 2 * BB * HH;
    float acc[2][2][3] = {};

    const int bb = tid >> 3, kq = tid & 7;
    for (int k0 = 0; k0 < HH; k0 += 32) {
        {
            float4 v = *(const float4*)&hprev[(b0 + bb)*HH + k0 + 4*kq];
            As[bb][4*kq+0] = v.x; As[bb][4*kq+1] = v.y;
            As[bb][4*kq+2] = v.z; As[bb][4*kq+3] = v.w;
        }
#pragma unroll
        for (int g = 0; g < 3; g++) {
            float4 v = *(const float4*)&P.Whh0[(g*HH + hc0 + bb)*HH + k0 + 4*kq];
            Ws[g][4*kq+0][bb] = v.x; Ws[g][4*kq+1][bb] = v.y;
            Ws[g][4*kq+2][bb] = v.z; Ws[g][4*kq+3][bb] = v.w;
        }
        __syncthreads();
#pragma unroll
        for (int kk = 0; kk < 32; kk++) {
            float a0 = As[2*ty + 0][kk], a1 = As[2*ty + 1][kk];
            float2 w0 = *(float2*)&Ws[0][kk][2*tx];
            float2 w1 = *(float2*)&Ws[1][kk][2*tx];
            float2 w2 = *(float2*)&Ws[2][kk][2*tx];
            acc[0][0][0] += a0*w0.x; acc[0][1][0] += a0*w0.y;
            acc[0][0][1] += a0*w1.x; acc[0][1][1] += a0*w1.y;
            acc[0][0][2] += a0*w2.x; acc[0][1][2] += a0*w2.y;
            acc[1][0][0] += a1*w0.x; acc[1][1][0] += a1*w0.y;
            acc[1][0][1] += a1*w1.x; acc[1][1][1] += a1*w1.y;
            acc[1][0][2] += a1*w2.x; acc[1][1][2] += a1*w2.y;
        }
        __syncthreads();
    }
#pragma unroll
    for (int r = 0; r < 2; r++) {
        int b = b0 + 2*ty + r;
        float x0 = recv[(b*TT + step)*2 + 0];
        float x1 = recv[(b*TT + step)*2 + 1];
#pragma unroll
        for (int c = 0; c < 2; c++) {
            int h = hc0 + 2*tx + c;
            float ir  = P.Wih0[h*2]          * x0 + P.Wih0[h*2 + 1]          * x1 + P.bih0[h];
            float iz  = P.Wih0[(HH + h)*2]   * x0 + P.Wih0[(HH + h)*2 + 1]   * x1 + P.bih0[HH + h];
            float in_ = P.Wih0[(2*HH + h)*2] * x0 + P.Wih0[(2*HH + h)*2 + 1] * x1 + P.bih0[2*HH + h];
            float hr = acc[r][c][0] + P.bhh0[h];
            float hz = acc[r][c][1] + P.bhh0[HH + h];
            float hn = acc[r][c][2] + P.bhh0[2*HH + h];
            float rg = sigm(ir + hr);
            float zg = sigm(iz + hz);
            float n  = tanhf(in_ + rg * hn);
            float hv = (1.0f - zg) * n + zg * hprev[b*HH + h];
            g_hnew[((s*2 + 0)*BB + b)*HH + h] = hv;
            g_buf[(((s*BB + b)*TT + step)*2 + 0)*HH + h] = hv;
        }
    }
}

// ---------------------------------------------------------------------------
// K2: GRU layer 1. Two fused GEMMs (x=h0 @ Wih1^T, h1 @ Whh1^T), same tiling.
// ---------------------------------------------------------------------------
__global__ __launch_bounds__(256) void k2_layer1(GruP p1, GruP p2, int step) {
    const int s = blockIdx.z;
    const GruP P = s ? p2 : p1;
    __shared__ float A1s[32][33], A2s[32][33];
    __shared__ float Wi[3][32][34], Wh[3][32][34];
    const int tid = threadIdx.x;
    const int tx = tid & 15, ty = tid >> 4;
    const int b0 = blockIdx.y * 32, hc0 = blockIdx.x * 32;
    const float* __restrict__ xin = g_hnew + (s*2 + 0) * BB * HH;
    const float* __restrict__ hp  = g_h    + (s*2 + 1) * BB * HH;
    float ai[2][2][3] = {}, ah[2][2][3] = {};

    const int bb = tid >> 3, kq = tid & 7;
    for (int k0 = 0; k0 < HH; k0 += 32) {
        {
            float4 v = *(const float4*)&xin[(b0 + bb)*HH + k0 + 4*kq];
            A1s[bb][4*kq+0] = v.x; A1s[bb][4*kq+1] = v.y;
            A1s[bb][4*kq+2] = v.z; A1s[bb][4*kq+3] = v.w;
            float4 u = *(const float4*)&hp[(b0 + bb)*HH + k0 + 4*kq];
            A2s[bb][4*kq+0] = u.x; A2s[bb][4*kq+1] = u.y;
            A2s[bb][4*kq+2] = u.z; A2s[bb][4*kq+3] = u.w;
        }
#pragma unroll
        for (int g = 0; g < 3; g++) {
            float4 v = *(const float4*)&P.Wih1[(g*HH + hc0 + bb)*HH + k0 + 4*kq];
            Wi[g][4*kq+0][bb] = v.x; Wi[g][4*kq+1][bb] = v.y;
            Wi[g][4*kq+2][bb] = v.z; Wi[g][4*kq+3][bb] = v.w;
            float4 u = *(const float4*)&P.Whh1[(g*HH + hc0 + bb)*HH + k0 + 4*kq];
            Wh[g][4*kq+0][bb] = u.x; Wh[g][4*kq+1][bb] = u.y;
            Wh[g][4*kq+2][bb] = u.z; Wh[g][4*kq+3][bb] = u.w;
        }
        __syncthreads();
#pragma unroll
        for (int kk = 0; kk < 32; kk++) {
            float x0v = A1s[2*ty + 0][kk], x1v = A1s[2*ty + 1][kk];
            float h0v = A2s[2*ty + 0][kk], h1v = A2s[2*ty + 1][kk];
#pragma unroll
            for (int g = 0; g < 3; g++) {
                float2 wi = *(float2*)&Wi[g][kk][2*tx];
                float2 wh = *(float2*)&Wh[g][kk][2*tx];
                ai[0][0][g] += x0v*wi.x; ai[0][1][g] += x0v*wi.y;
                ai[1][0][g] += x1v*wi.x; ai[1][1][g] += x1v*wi.y;
                ah[0][0][g] += h0v*wh.x; ah[0][1][g] += h0v*wh.y;
                ah[1][0][g] += h1v*wh.x; ah[1][1][g] += h1v*wh.y;
            }
        }
        __syncthreads();
    }
#pragma unroll
    for (int r = 0; r < 2; r++) {
        int b = b0 + 2*ty + r;
#pragma unroll
        for (int c = 0; c < 2; c++) {
            int h = hc0 + 2*tx + c;
            float ir  = ai[r][c][0] + P.bih1[h];
            float iz  = ai[r][c][1] + P.bih1[HH + h];
            float in_ = ai[r][c][2] + P.bih1[2*HH + h];
            float hr  = ah[r][c][0] + P.bhh1[h];
            float hz  = ah[r][c][1] + P.bhh1[HH + h];
            float hn  = ah[r][c][2] + P.bhh1[2*HH + h];
            float rg = sigm(ir + hr);
            float zg = sigm(iz + hz);
            float n  = tanhf(in_ + rg * hn);
            float hv = (1.0f - zg) * n + zg * hp[b*HH + h];
            g_hnew[((s*2 + 1)*BB + b)*HH + h] = hv;
            g_buf[(((s*BB + b)*TT + step)*2 + 1)*HH + h] = hv;
            g_out[((s*TT + step)*BB + b)*HH + h] = hv;
        }
    }
}

// ---------------------------------------------------------------------------
// K3: attention projections. Single GEMM M=1024, N=512 (es||eh), K=256.
// Tile 64m x 64n, BK=32, 4x4 micro-tile. A stored TRANSPOSED in smem:
// inner loop = 2x LDS.128 + 16 FFMA, conflict-free. grid (8 n, 16 m).
// ---------------------------------------------------------------------------
__global__ __launch_bounds__(256) void k3_proj(const float* __restrict__ attn_W, int step) {
    __shared__ float AsT[32][68];  // [k][m], 16B-aligned rows, conflict-free LDS.128
    __shared__ float Bs [32][68];  // [k][n]
    const int tid = threadIdx.x;
    const int tx = tid & 15, ty = tid >> 4;
    const int n0 = blockIdx.x * 64, m0 = blockIdx.y * 64;
    // B source: n<256 -> attn_W[n][k] ; n>=256 -> attn_W[n-256][256+k]
    const float* __restrict__ bsrc = (n0 < 256) ? (attn_W + n0*(2*HH))
                                                : (attn_W + (n0 - 256)*(2*HH) + HH);
    float acc[4][4] = {};

    for (int k0 = 0; k0 < HH; k0 += 32) {
#pragma unroll
        for (int i = 0; i < 2; i++) {
            int q = tid + i*256;
            int mm = q >> 3, kq = q & 7;
            float4 v = *(const float4*)&g_hnew[(m0 + mm)*HH + k0 + 4*kq];
            AsT[4*kq+0][mm] = v.x; AsT[4*kq+1][mm] = v.y;
            AsT[4*kq+2][mm] = v.z; AsT[4*kq+3][mm] = v.w;
            float4 u = *(const float4*)&bsrc[mm*(2*HH) + k0 + 4*kq];  // mm = nn here
            Bs[4*kq+0][mm] = u.x; Bs[4*kq+1][mm] = u.y;
            Bs[4*kq+2][mm] = u.z; Bs[4*kq+3][mm] = u.w;
        }
        __syncthreads();
#pragma unroll
        for (int kk = 0; kk < 32; kk++) {
            float4 av = *(float4*)&AsT[kk][4*ty];
            float4 bv = *(float4*)&Bs [kk][4*tx];
            acc[0][0] += av.x*bv.x; acc[0][1] += av.x*bv.y; acc[0][2] += av.x*bv.z; acc[0][3] += av.x*bv.w;
            acc[1][0] += av.y*bv.x; acc[1][1] += av.y*bv.y; acc[1][2] += av.y*bv.z; acc[1][3] += av.y*bv.w;
            acc[2][0] += av.z*bv.x; acc[2][1] += av.z*bv.y; acc[2][2] += av.z*bv.z; acc[2][3] += av.z*bv.w;
            acc[3][0] += av.w*bv.x; acc[3][1] += av.w*bv.y; acc[3][2] += av.w*bv.z; acc[3][3] += av.w*bv.w;
        }
        __syncthreads();
    }
#pragma unroll
    for (int r = 0; r < 4; r++) {
        int m = m0 + 4*ty + r;
        int s = m >> 9, l = (m >> 8) & 1, b = m & 255;
        if (n0 < 256) {
#pragma unroll
            for (int c = 0; c < 4; c++) g_es[m*HH + n0 + 4*tx + c] = acc[r][c];
        } else {
            float* dst = g_eh + (((s*BB + b)*TT + step)*2 + l)*HH + (n0 - 256) + 4*tx;
#pragma unroll
            for (int c = 0; c < 4; c++) dst[c] = acc[r][c];
        }
    }
}

// ---------------------------------------------------------------------------
// K4: attention energies (tanh.approx) + softmax + context. Block per (b, s).
// ---------------------------------------------------------------------------
__global__ __launch_bounds__(256) void k4_attend(const float* __restrict__ v_W, int step) {
    const int b = blockIdx.x, s = blockIdx.y;
    const int tid = threadIdx.x, warp = tid >> 5, lane = tid & 31;
    __shared__ float lg[2][2*TT];
    __shared__ float inv[2];
    const int nrows = 2 * (step + 1);

    const int l = warp & 1;
    float esr[8], vw0[8], vw1[8];
    {
        int gb = lane * 8;
        const float* esp = g_es + ((s*2 + l)*BB + b)*HH + gb;
#pragma unroll
        for (int u = 0; u < 8; u++) {
            esr[u] = esp[u];
            vw0[u] = v_W[gb + u];
            vw1[u] = v_W[HH + gb + u];
        }
    }
    const float* ehbase = g_eh + ((s*BB + b)*TT*2) * HH;
    for (int r = warp; r < nrows; r += 8) {
        const float4* ehp = (const float4*)(ehbase + r*HH) + lane*2;
        float4 ea = ehp[0], eb = ehp[1];
        float t0 = 0.0f, t1 = 0.0f, t;
#define ESTEP(u, e) { t = tanh_fast(esr[u] + (e)); t0 += t*vw0[u]; t1 += t*vw1[u]; }
        ESTEP(0, ea.x) ESTEP(1, ea.y) ESTEP(2, ea.z) ESTEP(3, ea.w)
        ESTEP(4, eb.x) ESTEP(5, eb.y) ESTEP(6, eb.z) ESTEP(7, eb.w)
#undef ESTEP
#pragma unroll
        for (int o = 16; o; o >>= 1) {
            t0 += __shfl_xor_sync(0xffffffffu, t0, o);
            t1 += __shfl_xor_sync(0xffffffffu, t1, o);
        }
        if (lane == 0) { lg[0][r] = t0; lg[1][r] = t1; }
    }
    __syncthreads();

    if (warp < 2) {
        int o = warp;
        float m = -1e30f;
        for (int r = lane; r < nrows; r += 32) m = fmaxf(m, lg[o][r]);
#pragma unroll
        for (int off = 16; off; off >>= 1) m = fmaxf(m, __shfl_xor_sync(0xffffffffu, m, off));
        float ss = 0.0f;
        for (int r = lane; r < nrows; r += 32) {
            float e = __expf(lg[o][r] - m);
            lg[o][r] = e;
            ss += e;
        }
#pragma unroll
        for (int off = 16; off; off >>= 1) ss += __shfl_xor_sync(0xffffffffu, ss, off);
        if (lane == 0) inv[o] = 1.0f / ss;
    }
    __syncthreads();

    const float* bufbase = g_buf + ((s*BB + b)*TT*2) * HH;
    float c0 = 0.0f, c1 = 0.0f;
    int r = 0;
    for (; r + 4 <= nrows; r += 4) {
        float v0 = bufbase[(r + 0)*HH + tid];
        float v1 = bufbase[(r + 1)*HH + tid];
        float v2 = bufbase[(r + 2)*HH + tid];
        float v3 = bufbase[(r + 3)*HH + tid];
        c0 += lg[0][r]*v0 + lg[0][r+1]*v1 + lg[0][r+2]*v2 + lg[0][r+3]*v3;
        c1 += lg[1][r]*v0 + lg[1][r+1]*v1 + lg[1][r+2]*v2 + lg[1][r+3]*v3;
    }
    for (; r < nrows; r++) {
        float v = bufbase[r*HH + tid];
        c0 += lg[0][r]*v;
        c1 += lg[1][r]*v;
    }
    g_ctx[((s*2 + 0)*BB + b)*HH + tid] = c0 * inv[0];
    g_ctx[((s*2 + 1)*BB + b)*HH + tid] = c1 * inv[1];
}

// ---------------------------------------------------------------------------
// K5: fc merge. GEMM M=1024 (rows = [s][o][b]), N=256, K=512 (A=[ctx|hnew]).
// Tile 64m x 32n, BK=32, 4x2 micro-tile, A transposed in smem. grid (8 n, 16 m).
// ---------------------------------------------------------------------------
__global__ __launch_bounds__(256) void k5_fc(const float* __restrict__ fc_W,
                                             const float* __restrict__ fc_b) {
    __shared__ float AsT[32][68];  // [k][m]
    __shared__ float Bs [32][36];  // [k][n]
    const int tid = threadIdx.x;
    const int tx = tid & 15, ty = tid >> 4;
    const int n0 = blockIdx.x * 32, m0 = blockIdx.y * 64;
    float acc[4][2] = {};

    for (int k0 = 0; k0 < 2*HH; k0 += 32) {
        const float* Asrc = (k0 < HH) ? g_ctx : g_hnew;
        const int ko = (k0 < HH) ? k0 : (k0 - HH);
#pragma unroll
        for (int i = 0; i < 2; i++) {
            int q = tid + i*256;
            int mm = q >> 3, kq = q & 7;
            float4 v = *(const float4*)&Asrc[(m0 + mm)*HH + ko + 4*kq];
            AsT[4*kq+0][mm] = v.x; AsT[4*kq+1][mm] = v.y;
            AsT[4*kq+2][mm] = v.z; AsT[4*kq+3][mm] = v.w;
        }
        {
            int nn = tid >> 3, kq = tid & 7;
            float4 u = *(const float4*)&fc_W[(n0 + nn)*(2*HH) + k0 + 4*kq];
            Bs[4*kq+0][nn] = u.x; Bs[4*kq+1][nn] = u.y;
            Bs[4*kq+2][nn] = u.z; Bs[4*kq+3][nn] = u.w;
        }
        __syncthreads();
#pragma unroll
        for (int kk = 0; kk < 32; kk++) {
            float4 av = *(float4*)&AsT[kk][4*ty];
            float2 bv = *(float2*)&Bs [kk][2*tx];
            acc[0][0] += av.x*bv.x; acc[0][1] += av.x*bv.y;
            acc[1][0] += av.y*bv.x; acc[1][1] += av.y*bv.y;
            acc[2][0] += av.z*bv.x; acc[2][1] += av.z*bv.y;
            acc[3][0] += av.w*bv.x; acc[3][1] += av.w*bv.y;
        }
        __syncthreads();
    }
#pragma unroll
    for (int r = 0; r < 4; r++) {
        int m = m0 + 4*ty + r;
#pragma unroll
        for (int c = 0; c < 2; c++) {
            int n = n0 + 2*tx + c;
            g_h[m*HH + n] = acc[r][c] + fc_b[n];
        }
    }
}

// ---------------------------------------------------------------------------
// K6: final readout: sigmoid([out1 | delayed out2] @ out_W^T + out_b)
// ---------------------------------------------------------------------------
__global__ __launch_bounds__(256) void k6_out(const float* __restrict__ out_W,
                                              const float* __restrict__ out_b,
                                              float* __restrict__ out) {
    const int t = blockIdx.x;
    const int tid = threadIdx.x, warp = tid >> 5, lane = tid & 31;
    __shared__ float w1[HH], w2[HH];
    w1[tid] = out_W[tid];
    w2[tid] = out_W[HH + tid];
    __syncthreads();
    int t2 = (t >= TT - DD - 1) ? (TT - 1) : (t + DD);
    float ob = out_b[0];
    const float* o1b = g_out + ((0*TT + t )*BB) * HH;
    const float* o2b = g_out + ((1*TT + t2)*BB) * HH;
    for (int bb = 0; bb < 32; bb++) {
        int b = warp*32 + bb;
        const float* o1 = o1b + b*HH;
        const float* o2 = o2b + b*HH;
        float acc = 0.0f;
#pragma unroll
        for (int h = lane; h < HH; h += 32) acc += o1[h]*w1[h] + o2[h]*w2[h];
#pragma unroll
        for (int off = 16; off; off >>= 1) acc += __shfl_xor_sync(0xffffffffu, acc, off);
        if (lane == 0) out[b*TT + t] = sigm(acc + ob);
    }
}

// ---------------------------------------------------------------------------
extern "C" void kernel_launch(void* const* d_in, const int* in_sizes, int n_in,
                              void* d_out, int out_size) {
    const float* recv = (const float*)d_in[0];
    GruP p1 { (const float*)d_in[1], (const float*)d_in[2], (const float*)d_in[3], (const float*)d_in[4],
              (const float*)d_in[5], (const float*)d_in[6], (const float*)d_in[7], (const float*)d_in[8] };
    GruP p2 { (const float*)d_in[9],  (const float*)d_in[10], (const float*)d_in[11], (const float*)d_in[12],
              (const float*)d_in[13], (const float*)d_in[14], (const float*)d_in[15], (const float*)d_in[16] };
    const float* fc_W   = (const float*)d_in[17];
    const float* fc_b   = (const float*)d_in[18];
    const float* attn_W = (const float*)d_in[19];
    const float* v_W    = (const float*)d_in[20];
    const float* out_W  = (const float*)d_in[21];
    const float* out_b  = (const float*)d_in[22];
    float* out = (float*)d_out;

    k_init<<<(2*2*BB*HH + 255)/256, 256>>>();

    for (int i = 0; i < TT; i++) {
        k1_layer0<<<dim3(8, 8, 2),  256>>>(recv, p1, p2, i);
        k2_layer1<<<dim3(8, 8, 2),  256>>>(p1, p2, i);
        k3_proj  <<<dim3(8, 16),    256>>>(attn_W, i);
        k4_attend<<<dim3(BB, 2),    256>>>(v_W, i);
        k5_fc    <<<dim3(8, 16),    256>>>(fc_W, fc_b);
    }
    k6_out<<<TT, 256>>>(out_W, out_b, out);
}

// round 9
// speedup vs baseline: 1.1714x; 1.1714x over previous
#include <cuda_runtime.h>
#include <math.h>

#define BB 256
#define TT 64
#define HH 256
#define DD 8

struct GruP {
    const float *Wih0, *Whh0, *bih0, *bhh0;
    const float *Wih1, *Whh1, *bih1, *bhh1;
};

// Persistent state (device globals: allocation-free scratch)
__device__ float g_h   [2*2*BB*HH];          // [s][l][b][h]  carried (post-attention) hidden
__device__ float g_hnew[2*2*BB*HH];          // [s][l][b][h]  fresh GRU hidden this step
__device__ float g_ctx [2*2*BB*HH];          // [s][o][b][h]  attention context
__device__ float g_es  [2*2*BB*HH];          // [s][l][b][g]  query projection
__device__ float g_buf [2*BB*TT*2*HH];       // [s][b][t][l][h]  hidden history
__device__ float g_eh  [2*BB*TT*2*HH];       // [s][b][t][l][g]  cached history projection
__device__ float g_out [2*TT*BB*HH];         // [s][t][b][h]  top-layer GRU outputs

__device__ __forceinline__ float sigm(float x) { return 1.0f / (1.0f + __expf(-x)); }
__device__ __forceinline__ float tanh_fast(float x) {
    float y;
    asm("tanh.approx.f32 %0, %1;" : "=f"(y) : "f"(x));
    return y;
}

__global__ void k_init() {
    int i = blockIdx.x * blockDim.x + threadIdx.x;
    if (i < 2*2*BB*HH) g_h[i] = 0.0f;
}

// ---------------------------------------------------------------------------
// K1: GRU layer 0. gh = h_prev @ Whh0^T fused with gate math.
// Ping-pong smem (1 sync/tile), LDG prefetch in regs, 1-stage LDS pipeline.
// ---------------------------------------------------------------------------
__global__ __launch_bounds__(256) void k1_layer0(const float* __restrict__ recv,
                                                 GruP p1, GruP p2, int step) {
    const int s = blockIdx.z;
    const GruP P = s ? p2 : p1;
    __shared__ float As[2][32][33];        // [buf][b][k]
    __shared__ float Ws[2][3][32][34];     // [buf][g][k][h]
    const int tid = threadIdx.x;
    const int tx = tid & 15, ty = tid >> 4;
    const int b0 = blockIdx.y * 32, hc0 = blockIdx.x * 32;
    const float* __restrict__ hprev = g_h + s * 2 * BB * HH;
    float acc[2][2][3] = {};

    const int bb = tid >> 3, kq = tid & 7;
    const float* aptr = &hprev[(b0 + bb)*HH + 4*kq];
    const float* wptr = &P.Whh0[(hc0 + bb)*HH + 4*kq];

    float4 pa  = *(const float4*)aptr;
    float4 pw0 = *(const float4*)(wptr);
    float4 pw1 = *(const float4*)(wptr + HH*HH);
    float4 pw2 = *(const float4*)(wptr + 2*HH*HH);

    int buf = 0;
    for (int k0 = 0; k0 < HH; k0 += 32) {
        As[buf][bb][4*kq+0] = pa.x; As[buf][bb][4*kq+1] = pa.y;
        As[buf][bb][4*kq+2] = pa.z; As[buf][bb][4*kq+3] = pa.w;
        Ws[buf][0][4*kq+0][bb] = pw0.x; Ws[buf][0][4*kq+1][bb] = pw0.y;
        Ws[buf][0][4*kq+2][bb] = pw0.z; Ws[buf][0][4*kq+3][bb] = pw0.w;
        Ws[buf][1][4*kq+0][bb] = pw1.x; Ws[buf][1][4*kq+1][bb] = pw1.y;
        Ws[buf][1][4*kq+2][bb] = pw1.z; Ws[buf][1][4*kq+3][bb] = pw1.w;
        Ws[buf][2][4*kq+0][bb] = pw2.x; Ws[buf][2][4*kq+1][bb] = pw2.y;
        Ws[buf][2][4*kq+2][bb] = pw2.z; Ws[buf][2][4*kq+3][bb] = pw2.w;
        __syncthreads();
        if (k0 + 32 < HH) {
            pa  = *(const float4*)(aptr + k0 + 32);
            pw0 = *(const float4*)(wptr + k0 + 32);
            pw1 = *(const float4*)(wptr + HH*HH + k0 + 32);
            pw2 = *(const float4*)(wptr + 2*HH*HH + k0 + 32);
        }
        float a0 = As[buf][2*ty + 0][0], a1 = As[buf][2*ty + 1][0];
        float2 w0 = *(float2*)&Ws[buf][0][0][2*tx];
        float2 w1 = *(float2*)&Ws[buf][1][0][2*tx];
        float2 w2 = *(float2*)&Ws[buf][2][0][2*tx];
#pragma unroll
        for (int kk = 0; kk < 32; kk++) {
            float a0n, a1n; float2 w0n, w1n, w2n;
            if (kk < 31) {
                a0n = As[buf][2*ty + 0][kk+1]; a1n = As[buf][2*ty + 1][kk+1];
                w0n = *(float2*)&Ws[buf][0][kk+1][2*tx];
                w1n = *(float2*)&Ws[buf][1][kk+1][2*tx];
                w2n = *(float2*)&Ws[buf][2][kk+1][2*tx];
            }
            acc[0][0][0] += a0*w0.x; acc[0][1][0] += a0*w0.y;
            acc[0][0][1] += a0*w1.x; acc[0][1][1] += a0*w1.y;
            acc[0][0][2] += a0*w2.x; acc[0][1][2] += a0*w2.y;
            acc[1][0][0] += a1*w0.x; acc[1][1][0] += a1*w0.y;
            acc[1][0][1] += a1*w1.x; acc[1][1][1] += a1*w1.y;
            acc[1][0][2] += a1*w2.x; acc[1][1][2] += a1*w2.y;
            a0 = a0n; a1 = a1n; w0 = w0n; w1 = w1n; w2 = w2n;
        }
        buf ^= 1;
    }
#pragma unroll
    for (int r = 0; r < 2; r++) {
        int b = b0 + 2*ty + r;
        float x0 = recv[(b*TT + step)*2 + 0];
        float x1 = recv[(b*TT + step)*2 + 1];
#pragma unroll
        for (int c = 0; c < 2; c++) {
            int h = hc0 + 2*tx + c;
            float ir  = P.Wih0[h*2]          * x0 + P.Wih0[h*2 + 1]          * x1 + P.bih0[h];
            float iz  = P.Wih0[(HH + h)*2]   * x0 + P.Wih0[(HH + h)*2 + 1]   * x1 + P.bih0[HH + h];
            float in_ = P.Wih0[(2*HH + h)*2] * x0 + P.Wih0[(2*HH + h)*2 + 1] * x1 + P.bih0[2*HH + h];
            float hr = acc[r][c][0] + P.bhh0[h];
            float hz = acc[r][c][1] + P.bhh0[HH + h];
            float hn = acc[r][c][2] + P.bhh0[2*HH + h];
            float rg = sigm(ir + hr);
            float zg = sigm(iz + hz);
            float n  = tanhf(in_ + rg * hn);
            float hv = (1.0f - zg) * n + zg * hprev[b*HH + h];
            g_hnew[((s*2 + 0)*BB + b)*HH + h] = hv;
            g_buf[(((s*BB + b)*TT + step)*2 + 0)*HH + h] = hv;
        }
    }
}

// ---------------------------------------------------------------------------
// K2: GRU layer 1. Two fused GEMMs. Single-buffered smem (cap), but LDG
// prefetch overlaps compute; 1-stage LDS pipeline in inner loop.
// ---------------------------------------------------------------------------
__global__ __launch_bounds__(256) void k2_layer1(GruP p1, GruP p2, int step) {
    const int s = blockIdx.z;
    const GruP P = s ? p2 : p1;
    __shared__ float A1s[32][33], A2s[32][33];
    __shared__ float Wi[3][32][34], Wh[3][32][34];
    const int tid = threadIdx.x;
    const int tx = tid & 15, ty = tid >> 4;
    const int b0 = blockIdx.y * 32, hc0 = blockIdx.x * 32;
    const float* __restrict__ xin = g_hnew + (s*2 + 0) * BB * HH;
    const float* __restrict__ hp  = g_h    + (s*2 + 1) * BB * HH;
    float ai[2][2][3] = {}, ah[2][2][3] = {};

    const int bb = tid >> 3, kq = tid & 7;
    const float* a1ptr = &xin[(b0 + bb)*HH + 4*kq];
    const float* a2ptr = &hp [(b0 + bb)*HH + 4*kq];
    const float* wiptr = &P.Wih1[(hc0 + bb)*HH + 4*kq];
    const float* whptr = &P.Whh1[(hc0 + bb)*HH + 4*kq];

    float4 pa1 = *(const float4*)a1ptr;
    float4 pa2 = *(const float4*)a2ptr;
    float4 pi0 = *(const float4*)(wiptr);
    float4 pi1 = *(const float4*)(wiptr + HH*HH);
    float4 pi2 = *(const float4*)(wiptr + 2*HH*HH);
    float4 ph0 = *(const float4*)(whptr);
    float4 ph1 = *(const float4*)(whptr + HH*HH);
    float4 ph2 = *(const float4*)(whptr + 2*HH*HH);

    for (int k0 = 0; k0 < HH; k0 += 32) {
        A1s[bb][4*kq+0] = pa1.x; A1s[bb][4*kq+1] = pa1.y;
        A1s[bb][4*kq+2] = pa1.z; A1s[bb][4*kq+3] = pa1.w;
        A2s[bb][4*kq+0] = pa2.x; A2s[bb][4*kq+1] = pa2.y;
        A2s[bb][4*kq+2] = pa2.z; A2s[bb][4*kq+3] = pa2.w;
        Wi[0][4*kq+0][bb] = pi0.x; Wi[0][4*kq+1][bb] = pi0.y;
        Wi[0][4*kq+2][bb] = pi0.z; Wi[0][4*kq+3][bb] = pi0.w;
        Wi[1][4*kq+0][bb] = pi1.x; Wi[1][4*kq+1][bb] = pi1.y;
        Wi[1][4*kq+2][bb] = pi1.z; Wi[1][4*kq+3][bb] = pi1.w;
        Wi[2][4*kq+0][bb] = pi2.x; Wi[2][4*kq+1][bb] = pi2.y;
        Wi[2][4*kq+2][bb] = pi2.z; Wi[2][4*kq+3][bb] = pi2.w;
        Wh[0][4*kq+0][bb] = ph0.x; Wh[0][4*kq+1][bb] = ph0.y;
        Wh[0][4*kq+2][bb] = ph0.z; Wh[0][4*kq+3][bb] = ph0.w;
        Wh[1][4*kq+0][bb] = ph1.x; Wh[1][4*kq+1][bb] = ph1.y;
        Wh[1][4*kq+2][bb] = ph1.z; Wh[1][4*kq+3][bb] = ph1.w;
        Wh[2][4*kq+0][bb] = ph2.x; Wh[2][4*kq+1][bb] = ph2.y;
        Wh[2][4*kq+2][bb] = ph2.z; Wh[2][4*kq+3][bb] = ph2.w;
        __syncthreads();
        if (k0 + 32 < HH) {
            pa1 = *(const float4*)(a1ptr + k0 + 32);
            pa2 = *(const float4*)(a2ptr + k0 + 32);
            pi0 = *(const float4*)(wiptr + k0 + 32);
            pi1 = *(const float4*)(wiptr + HH*HH + k0 + 32);
            pi2 = *(const float4*)(wiptr + 2*HH*HH + k0 + 32);
            ph0 = *(const float4*)(whptr + k0 + 32);
            ph1 = *(const float4*)(whptr + HH*HH + k0 + 32);
            ph2 = *(const float4*)(whptr + 2*HH*HH + k0 + 32);
        }
        float x0v = A1s[2*ty + 0][0], x1v = A1s[2*ty + 1][0];
        float h0v = A2s[2*ty + 0][0], h1v = A2s[2*ty + 1][0];
        float2 wi0 = *(float2*)&Wi[0][0][2*tx];
        float2 wi1 = *(float2*)&Wi[1][0][2*tx];
        float2 wi2 = *(float2*)&Wi[2][0][2*tx];
        float2 wh0 = *(float2*)&Wh[0][0][2*tx];
        float2 wh1 = *(float2*)&Wh[1][0][2*tx];
        float2 wh2 = *(float2*)&Wh[2][0][2*tx];
#pragma unroll
        for (int kk = 0; kk < 32; kk++) {
            float x0n, x1n, h0n, h1n;
            float2 wi0n, wi1n, wi2n, wh0n, wh1n, wh2n;
            if (kk < 31) {
                x0n = A1s[2*ty + 0][kk+1]; x1n = A1s[2*ty + 1][kk+1];
                h0n = A2s[2*ty + 0][kk+1]; h1n = A2s[2*ty + 1][kk+1];
                wi0n = *(float2*)&Wi[0][kk+1][2*tx];
                wi1n = *(float2*)&Wi[1][kk+1][2*tx];
                wi2n = *(float2*)&Wi[2][kk+1][2*tx];
                wh0n = *(float2*)&Wh[0][kk+1][2*tx];
                wh1n = *(float2*)&Wh[1][kk+1][2*tx];
                wh2n = *(float2*)&Wh[2][kk+1][2*tx];
            }
            ai[0][0][0] += x0v*wi0.x; ai[0][1][0] += x0v*wi0.y;
            ai[1][0][0] += x1v*wi0.x; ai[1][1][0] += x1v*wi0.y;
            ai[0][0][1] += x0v*wi1.x; ai[0][1][1] += x0v*wi1.y;
            ai[1][0][1] += x1v*wi1.x; ai[1][1][1] += x1v*wi1.y;
            ai[0][0][2] += x0v*wi2.x; ai[0][1][2] += x0v*wi2.y;
            ai[1][0][2] += x1v*wi2.x; ai[1][1][2] += x1v*wi2.y;
            ah[0][0][0] += h0v*wh0.x; ah[0][1][0] += h0v*wh0.y;
            ah[1][0][0] += h1v*wh0.x; ah[1][1][0] += h1v*wh0.y;
            ah[0][0][1] += h0v*wh1.x; ah[0][1][1] += h0v*wh1.y;
            ah[1][0][1] += h1v*wh1.x; ah[1][1][1] += h1v*wh1.y;
            ah[0][0][2] += h0v*wh2.x; ah[0][1][2] += h0v*wh2.y;
            ah[1][0][2] += h1v*wh2.x; ah[1][1][2] += h1v*wh2.y;
            x0v = x0n; x1v = x1n; h0v = h0n; h1v = h1n;
            wi0 = wi0n; wi1 = wi1n; wi2 = wi2n;
            wh0 = wh0n; wh1 = wh1n; wh2 = wh2n;
        }
        __syncthreads();
    }
#pragma unroll
    for (int r = 0; r < 2; r++) {
        int b = b0 + 2*ty + r;
#pragma unroll
        for (int c = 0; c < 2; c++) {
            int h = hc0 + 2*tx + c;
            float ir  = ai[r][c][0] + P.bih1[h];
            float iz  = ai[r][c][1] + P.bih1[HH + h];
            float in_ = ai[r][c][2] + P.bih1[2*HH + h];
            float hr  = ah[r][c][0] + P.bhh1[h];
            float hz  = ah[r][c][1] + P.bhh1[HH + h];
            float hn  = ah[r][c][2] + P.bhh1[2*HH + h];
            float rg = sigm(ir + hr);
            float zg = sigm(iz + hz);
            float n  = tanhf(in_ + rg * hn);
            float hv = (1.0f - zg) * n + zg * hp[b*HH + h];
            g_hnew[((s*2 + 1)*BB + b)*HH + h] = hv;
            g_buf[(((s*BB + b)*TT + step)*2 + 1)*HH + h] = hv;
            g_out[((s*TT + step)*BB + b)*HH + h] = hv;
        }
    }
}

// ---------------------------------------------------------------------------
// K3: attention projections. GEMM M=1024, N=512 (es||eh), K=256.
// 64x64 tile, 4x4 micro-tile, ping-pong smem, LDG prefetch, LDS pipeline.
// ---------------------------------------------------------------------------
__global__ __launch_bounds__(256) void k3_proj(const float* __restrict__ attn_W, int step) {
    __shared__ float AsT[2][32][68];  // [buf][k][m]
    __shared__ float Bs [2][32][68];  // [buf][k][n]
    const int tid = threadIdx.x;
    const int tx = tid & 15, ty = tid >> 4;
    const int n0 = blockIdx.x * 64, m0 = blockIdx.y * 64;
    const float* __restrict__ bsrc = (n0 < 256) ? (attn_W + n0*(2*HH))
                                                : (attn_W + (n0 - 256)*(2*HH) + HH);
    float acc[4][4] = {};

    const int mm = tid >> 3, kq = tid & 7;
    const float* aptr0 = &g_hnew[(m0 + mm)*HH + 4*kq];
    const float* aptr1 = &g_hnew[(m0 + mm + 32)*HH + 4*kq];
    const float* bptr0 = &bsrc[mm*(2*HH) + 4*kq];
    const float* bptr1 = &bsrc[(mm + 32)*(2*HH) + 4*kq];

    float4 pa0 = *(const float4*)aptr0;
    float4 pa1 = *(const float4*)aptr1;
    float4 pb0 = *(const float4*)bptr0;
    float4 pb1 = *(const float4*)bptr1;

    int buf = 0;
    for (int k0 = 0; k0 < HH; k0 += 32) {
        AsT[buf][4*kq+0][mm] = pa0.x; AsT[buf][4*kq+1][mm] = pa0.y;
        AsT[buf][4*kq+2][mm] = pa0.z; AsT[buf][4*kq+3][mm] = pa0.w;
        AsT[buf][4*kq+0][mm+32] = pa1.x; AsT[buf][4*kq+1][mm+32] = pa1.y;
        AsT[buf][4*kq+2][mm+32] = pa1.z; AsT[buf][4*kq+3][mm+32] = pa1.w;
        Bs[buf][4*kq+0][mm] = pb0.x; Bs[buf][4*kq+1][mm] = pb0.y;
        Bs[buf][4*kq+2][mm] = pb0.z; Bs[buf][4*kq+3][mm] = pb0.w;
        Bs[buf][4*kq+0][mm+32] = pb1.x; Bs[buf][4*kq+1][mm+32] = pb1.y;
        Bs[buf][4*kq+2][mm+32] = pb1.z; Bs[buf][4*kq+3][mm+32] = pb1.w;
        __syncthreads();
        if (k0 + 32 < HH) {
            pa0 = *(const float4*)(aptr0 + k0 + 32);
            pa1 = *(const float4*)(aptr1 + k0 + 32);
            pb0 = *(const float4*)(bptr0 + k0 + 32);
            pb1 = *(const float4*)(bptr1 + k0 + 32);
        }
        float4 av = *(float4*)&AsT[buf][0][4*ty];
        float4 bv = *(float4*)&Bs [buf][0][4*tx];
#pragma unroll
        for (int kk = 0; kk < 32; kk++) {
            float4 avn, bvn;
            if (kk < 31) {
                avn = *(float4*)&AsT[buf][kk+1][4*ty];
                bvn = *(float4*)&Bs [buf][kk+1][4*tx];
            }
            acc[0][0] += av.x*bv.x; acc[0][1] += av.x*bv.y; acc[0][2] += av.x*bv.z; acc[0][3] += av.x*bv.w;
            acc[1][0] += av.y*bv.x; acc[1][1] += av.y*bv.y; acc[1][2] += av.y*bv.z; acc[1][3] += av.y*bv.w;
            acc[2][0] += av.z*bv.x; acc[2][1] += av.z*bv.y; acc[2][2] += av.z*bv.z; acc[2][3] += av.z*bv.w;
            acc[3][0] += av.w*bv.x; acc[3][1] += av.w*bv.y; acc[3][2] += av.w*bv.z; acc[3][3] += av.w*bv.w;
            av = avn; bv = bvn;
        }
        buf ^= 1;
    }
#pragma unroll
    for (int r = 0; r < 4; r++) {
        int m = m0 + 4*ty + r;
        int s = m >> 9, l = (m >> 8) & 1, b = m & 255;
        if (n0 < 256) {
#pragma unroll
            for (int c = 0; c < 4; c++) g_es[m*HH + n0 + 4*tx + c] = acc[r][c];
        } else {
            float* dst = g_eh + (((s*BB + b)*TT + step)*2 + l)*HH + (n0 - 256) + 4*tx;
#pragma unroll
            for (int c = 0; c < 4; c++) dst[c] = acc[r][c];
        }
    }
}

// ---------------------------------------------------------------------------
// K4: attention energies (tanh.approx) + softmax + context. Block per (b, s).
// ---------------------------------------------------------------------------
__global__ __launch_bounds__(256) void k4_attend(const float* __restrict__ v_W, int step) {
    const int b = blockIdx.x, s = blockIdx.y;
    const int tid = threadIdx.x, warp = tid >> 5, lane = tid & 31;
    __shared__ float lg[2][2*TT];
    __shared__ float inv[2];
    const int nrows = 2 * (step + 1);

    const int l = warp & 1;
    float esr[8], vw0[8], vw1[8];
    {
        int gb = lane * 8;
        const float* esp = g_es + ((s*2 + l)*BB + b)*HH + gb;
#pragma unroll
        for (int u = 0; u < 8; u++) {
            esr[u] = esp[u];
            vw0[u] = v_W[gb + u];
            vw1[u] = v_W[HH + gb + u];
        }
    }
    const float* ehbase = g_eh + ((s*BB + b)*TT*2) * HH;
    for (int r = warp; r < nrows; r += 8) {
        const float4* ehp = (const float4*)(ehbase + r*HH) + lane*2;
        float4 ea = ehp[0], eb = ehp[1];
        float t0 = 0.0f, t1 = 0.0f, t;
#define ESTEP(u, e) { t = tanh_fast(esr[u] + (e)); t0 += t*vw0[u]; t1 += t*vw1[u]; }
        ESTEP(0, ea.x) ESTEP(1, ea.y) ESTEP(2, ea.z) ESTEP(3, ea.w)
        ESTEP(4, eb.x) ESTEP(5, eb.y) ESTEP(6, eb.z) ESTEP(7, eb.w)
#undef ESTEP
#pragma unroll
        for (int o = 16; o; o >>= 1) {
            t0 += __shfl_xor_sync(0xffffffffu, t0, o);
            t1 += __shfl_xor_sync(0xffffffffu, t1, o);
        }
        if (lane == 0) { lg[0][r] = t0; lg[1][r] = t1; }
    }
    __syncthreads();

    if (warp < 2) {
        int o = warp;
        float m = -1e30f;
        for (int r = lane; r < nrows; r += 32) m = fmaxf(m, lg[o][r]);
#pragma unroll
        for (int off = 16; off; off >>= 1) m = fmaxf(m, __shfl_xor_sync(0xffffffffu, m, off));
        float ss = 0.0f;
        for (int r = lane; r < nrows; r += 32) {
            float e = __expf(lg[o][r] - m);
            lg[o][r] = e;
            ss += e;
        }
#pragma unroll
        for (int off = 16; off; off >>= 1) ss += __shfl_xor_sync(0xffffffffu, ss, off);
        if (lane == 0) inv[o] = 1.0f / ss;
    }
    __syncthreads();

    const float* bufbase = g_buf + ((s*BB + b)*TT*2) * HH;
    float c0 = 0.0f, c1 = 0.0f;
    int r = 0;
    for (; r + 4 <= nrows; r += 4) {
        float v0 = bufbase[(r + 0)*HH + tid];
        float v1 = bufbase[(r + 1)*HH + tid];
        float v2 = bufbase[(r + 2)*HH + tid];
        float v3 = bufbase[(r + 3)*HH + tid];
        c0 += lg[0][r]*v0 + lg[0][r+1]*v1 + lg[0][r+2]*v2 + lg[0][r+3]*v3;
        c1 += lg[1][r]*v0 + lg[1][r+1]*v1 + lg[1][r+2]*v2 + lg[1][r+3]*v3;
    }
    for (; r < nrows; r++) {
        float v = bufbase[r*HH + tid];
        c0 += lg[0][r]*v;
        c1 += lg[1][r]*v;
    }
    g_ctx[((s*2 + 0)*BB + b)*HH + tid] = c0 * inv[0];
    g_ctx[((s*2 + 1)*BB + b)*HH + tid] = c1 * inv[1];
}

// ---------------------------------------------------------------------------
// K5: fc merge. GEMM M=1024, N=256, K=512 (A=[ctx|hnew]).
// 64m x 32n tile, 4x2 micro-tile, ping-pong smem, LDG prefetch, LDS pipeline.
// ---------------------------------------------------------------------------
__global__ __launch_bounds__(256) void k5_fc(const float* __restrict__ fc_W,
                                             const float* __restrict__ fc_b) {
    __shared__ float AsT[2][32][68];  // [buf][k][m]
    __shared__ float Bs [2][32][36];  // [buf][k][n]
    const int tid = threadIdx.x;
    const int tx = tid & 15, ty = tid >> 4;
    const int n0 = blockIdx.x * 32, m0 = blockIdx.y * 64;
    float acc[4][2] = {};

    const int mm = tid >> 3, kq = tid & 7;
    const float* bptr = &fc_W[(n0 + (tid >> 3))*(2*HH) + 4*kq];

    auto loadA = [&](int k0, float4& a0, float4& a1) {
        const float* Asrc = (k0 < HH) ? g_ctx : g_hnew;
        const int ko = (k0 < HH) ? k0 : (k0 - HH);
        a0 = *(const float4*)&Asrc[(m0 + mm)*HH + ko + 4*kq];
        a1 = *(const float4*)&Asrc[(m0 + mm + 32)*HH + ko + 4*kq];
    };

    float4 pa0, pa1, pb;
    loadA(0, pa0, pa1);
    pb = *(const float4*)bptr;

    int buf = 0;
    for (int k0 = 0; k0 < 2*HH; k0 += 32) {
        AsT[buf][4*kq+0][mm] = pa0.x; AsT[buf][4*kq+1][mm] = pa0.y;
        AsT[buf][4*kq+2][mm] = pa0.z; AsT[buf][4*kq+3][mm] = pa0.w;
        AsT[buf][4*kq+0][mm+32] = pa1.x; AsT[buf][4*kq+1][mm+32] = pa1.y;
        AsT[buf][4*kq+2][mm+32] = pa1.z; AsT[buf][4*kq+3][mm+32] = pa1.w;
        Bs[buf][4*kq+0][mm] = pb.x; Bs[buf][4*kq+1][mm] = pb.y;
        Bs[buf][4*kq+2][mm] = pb.z; Bs[buf][4*kq+3][mm] = pb.w;
        __syncthreads();
        if (k0 + 32 < 2*HH) {
            loadA(k0 + 32, pa0, pa1);
            pb = *(const float4*)(bptr + k0 + 32);
        }
        float4 av = *(float4*)&AsT[buf][0][4*ty];
        float2 bv = *(float2*)&Bs [buf][0][2*tx];
#pragma unroll
        for (int kk = 0; kk < 32; kk++) {
            float4 avn; float2 bvn;
            if (kk < 31) {
                avn = *(float4*)&AsT[buf][kk+1][4*ty];
                bvn = *(float2*)&Bs [buf][kk+1][2*tx];
            }
            acc[0][0] += av.x*bv.x; acc[0][1] += av.x*bv.y;
            acc[1][0] += av.y*bv.x; acc[1][1] += av.y*bv.y;
            acc[2][0] += av.z*bv.x; acc[2][1] += av.z*bv.y;
            acc[3][0] += av.w*bv.x; acc[3][1] += av.w*bv.y;
            av = avn; bv = bvn;
        }
        buf ^= 1;
    }
#pragma unroll
    for (int r = 0; r < 4; r++) {
        int m = m0 + 4*ty + r;
#pragma unroll
        for (int c = 0; c < 2; c++) {
            int n = n0 + 2*tx + c;
            g_h[m*HH + n] = acc[r][c] + fc_b[n];
        }
    }
}

// ---------------------------------------------------------------------------
// K6: final readout: sigmoid([out1 | delayed out2] @ out_W^T + out_b)
// ---------------------------------------------------------------------------
__global__ __launch_bounds__(256) void k6_out(const float* __restrict__ out_W,
                                              const float* __restrict__ out_b,
                                              float* __restrict__ out) {
    const int t = blockIdx.x;
    const int tid = threadIdx.x, warp = tid >> 5, lane = tid & 31;
    __shared__ float w1[HH], w2[HH];
    w1[tid] = out_W[tid];
    w2[tid] = out_W[HH + tid];
    __syncthreads();
    int t2 = (t >= TT - DD - 1) ? (TT - 1) : (t + DD);
    float ob = out_b[0];
    const float* o1b = g_out + ((0*TT + t )*BB) * HH;
    const float* o2b = g_out + ((1*TT + t2)*BB) * HH;
    for (int bb = 0; bb < 32; bb++) {
        int b = warp*32 + bb;
        const float* o1 = o1b + b*HH;
        const float* o2 = o2b + b*HH;
        float acc = 0.0f;
#pragma unroll
        for (int h = lane; h < HH; h += 32) acc += o1[h]*w1[h] + o2[h]*w2[h];
#pragma unroll
        for (int off = 16; off; off >>= 1) acc += __shfl_xor_sync(0xffffffffu, acc, off);
        if (lane == 0) out[b*TT + t] = sigm(acc + ob);
    }
}

// ---------------------------------------------------------------------------
extern "C" void kernel_launch(void* const* d_in, const int* in_sizes, int n_in,
                              void* d_out, int out_size) {
    const float* recv = (const float*)d_in[0];
    GruP p1 { (const float*)d_in[1], (const float*)d_in[2], (const float*)d_in[3], (const float*)d_in[4],
              (const float*)d_in[5], (const float*)d_in[6], (const float*)d_in[7], (const float*)d_in[8] };
    GruP p2 { (const float*)d_in[9],  (const float*)d_in[10], (const float*)d_in[11], (const float*)d_in[12],
              (const float*)d_in[13], (const float*)d_in[14], (const float*)d_in[15], (const float*)d_in[16] };
    const float* fc_W   = (const float*)d_in[17];
    const float* fc_b   = (const float*)d_in[18];
    const float* attn_W = (const float*)d_in[19];
    const float* v_W    = (const float*)d_in[20];
    const float* out_W  = (const float*)d_in[21];
    const float* out_b  = (const float*)d_in[22];
    float* out = (float*)d_out;

    k_init<<<(2*2*BB*HH + 255)/256, 256>>>();

    for (int i = 0; i < TT; i++) {
        k1_layer0<<<dim3(8, 8, 2),  256>>>(recv, p1, p2, i);
        k2_layer1<<<dim3(8, 8, 2),  256>>>(p1, p2, i);
        if (i < TT - 1) {   // attention+fc only feed the NEXT step's hidden state
            k3_proj  <<<dim3(8, 16),    256>>>(attn_W, i);
            k4_attend<<<dim3(BB, 2),    256>>>(v_W, i);
            k5_fc    <<<dim3(8, 16),    256>>>(fc_W, fc_b);
        }
    }
    k6_out<<<TT, 256>>>(out_W, out_b, out);
}